// round 14
// baseline (speedup 1.0000x reference)
#include <cuda_runtime.h>
#include <math.h>

#define IMG_H 1500
#define IMG_W 2000
#define HW    (IMG_H * IMG_W)
#define NUM_V 10
#define NSLOT 32

// ---------------- device scratch (static; no runtime allocation) ----------------
// Quad layout: entry (x,y) = uint4 with the full 2x2 bilinear footprint.
//   .x = pixel(x,y)  .y = pixel(x+1,y)  .z = pixel(x,y+1)  .w = pixel(x+1,y+1)
// Each pixel packs r/g/b as 10-bit fixed point: (r<<20)|(g<<10)|b.
__device__ uint4 g_img1[HW];   // 48 MB
__device__ uint4 g_img2[HW];   // 48 MB
__device__ double g_sim[NSLOT];
__device__ double g_nrm[NSLOT];
__device__ double g_nz[NSLOT];
__device__ unsigned long long g_cnt[NSLOT];
__device__ float  g_T[12];     // rows 0..2 of K2h @ E2 @ inv(E1)

// ---------------- init: fp32, parallel prefetch, fast -----------------------
__global__ void k_init(const float* __restrict__ K2,
                       const float* __restrict__ E1,
                       const float* __restrict__ E2) {
    __shared__ float sE1[16], sE2[16], sK2[9];
    int t = threadIdx.x;
    if (t < 16) sE1[t] = E1[t];
    if (t < 16) sE2[t] = E2[t];
    if (t < 9)  sK2[t] = K2[t];
    if (t < NSLOT) { g_sim[t] = 0.0; g_nrm[t] = 0.0; g_nz[t] = 0.0; g_cnt[t] = 0ull; }
    __syncthreads();

    if (t == 0) {
        float a[4][8];
        for (int i = 0; i < 4; i++)
            for (int j = 0; j < 4; j++) {
                a[i][j] = sE1[i * 4 + j];
                a[i][4 + j] = (i == j) ? 1.0f : 0.0f;
            }
        for (int c = 0; c < 4; c++) {
            int p = c; float mx = fabsf(a[c][c]);
            for (int r = c + 1; r < 4; r++) {
                float v = fabsf(a[r][c]);
                if (v > mx) { mx = v; p = r; }
            }
            if (p != c)
                for (int j = 0; j < 8; j++) { float tmp = a[c][j]; a[c][j] = a[p][j]; a[p][j] = tmp; }
            float ipv = 1.0f / a[c][c];
            for (int j = 0; j < 8; j++) a[c][j] *= ipv;
            for (int r = 0; r < 4; r++)
                if (r != c) {
                    float f = a[r][c];
                    for (int j = 0; j < 8; j++) a[r][j] = fmaf(-f, a[c][j], a[r][j]);
                }
        }
        float M[4][4];
        for (int i = 0; i < 4; i++)
            for (int j = 0; j < 4; j++) {
                float s = 0.0f;
                for (int k = 0; k < 4; k++) s = fmaf(sE2[i * 4 + k], a[k][4 + j], s);
                M[i][j] = s;
            }
        for (int r = 0; r < 3; r++)
            for (int j = 0; j < 4; j++) {
                float s = 0.0f;
                for (int k = 0; k < 3; k++) s = fmaf(sK2[r * 3 + k], M[k][j], s);
                g_T[r * 4 + j] = s;
            }
    }
}

__device__ __forceinline__ unsigned int pack10(float r, float g, float b) {
    unsigned int qr = min(1023u, __float2uint_rn(r * 1023.0f));
    unsigned int qg = min(1023u, __float2uint_rn(g * 1023.0f));
    unsigned int qb = min(1023u, __float2uint_rn(b * 1023.0f));
    return (qr << 20) | (qg << 10) | qb;
}

// ---------------- pack both planar images -> 2x2 quad entries -------------------
__global__ void __launch_bounds__(256) k_pack(const float* __restrict__ r1,
                                              const float* __restrict__ r2) {
    int i = blockIdx.x * blockDim.x + threadIdx.x;
    if (i >= 2 * HW) return;
    const float* src = (i < HW) ? r1 : r2;
    uint4* dst       = (i < HW) ? g_img1 : g_img2;
    int j = (i < HW) ? i : i - HW;
    int x = j % IMG_W, y = j / IMG_W;
    int x1 = x + 1 < IMG_W ? x + 1 : IMG_W - 1;
    int y1 = y + 1 < IMG_H ? y + 1 : IMG_H - 1;

    int i00 = y * IMG_W + x,   i01 = y * IMG_W + x1;
    int i10 = y1 * IMG_W + x,  i11 = y1 * IMG_W + x1;

    uint4 v;
    v.x = pack10(src[i00], src[i00 + HW], src[i00 + 2 * HW]);
    v.y = pack10(src[i01], src[i01 + HW], src[i01 + 2 * HW]);
    v.z = pack10(src[i10], src[i10 + HW], src[i10 + 2 * HW]);
    v.w = pack10(src[i11], src[i11 + HW], src[i11 + 2 * HW]);
    dst[j] = v;
}

// ---------------- bilinear sample: ONE LDG.128 per sample ----------------
__device__ __forceinline__ float3 bilerp(const uint4* __restrict__ im, float uu, float vv) {
    float x = uu * (float)(IMG_W - 1);
    float y = vv * (float)(IMG_H - 1);
    float fx = floorf(x), fy = floorf(y);
    float wx = x - fx, wy = y - fy;
    int b = (int)fy * IMG_W + (int)fx;        // fx<=W-2, fy<=H-2 guaranteed by clip

    uint4 q = __ldg(im + b);

    const float s = 1.0f / 1023.0f;
    float w00 = (1.0f - wx) * (1.0f - wy) * s;
    float w01 = wx * (1.0f - wy) * s;
    float w10 = (1.0f - wx) * wy * s;
    float w11 = wx * wy * s;

    float3 r;
    r.x = w00 * (float)(q.x >> 20)
        + w01 * (float)(q.y >> 20)
        + w10 * (float)(q.z >> 20)
        + w11 * (float)(q.w >> 20);
    r.y = w00 * (float)((q.x >> 10) & 1023u)
        + w01 * (float)((q.y >> 10) & 1023u)
        + w10 * (float)((q.z >> 10) & 1023u)
        + w11 * (float)((q.w >> 10) & 1023u);
    r.z = w00 * (float)(q.x & 1023u)
        + w01 * (float)(q.y & 1023u)
        + w10 * (float)(q.z & 1023u)
        + w11 * (float)(q.w & 1023u);
    return r;
}

// ---- per-edge prep + sampling (block=edge, 10 warps, warp w owns dv=w) ---------
__global__ void __launch_bounds__(320) k_sample(const float* __restrict__ ep,
                                                const float* __restrict__ K1g) {
    int e = blockIdx.x;
    int wid  = threadIdx.x >> 5;    // 0..9  == dv
    int lane = threadIdx.x & 31;

    const float* pe = ep + (size_t)e * 12;
    float p0x = pe[0],  p0y = pe[1],  p0z = pe[2];
    float p1x = pe[3],  p1y = pe[4],  p1z = pe[5];
    float p2x = pe[6],  p2y = pe[7],  p2z = pe[8];
    float p3x = pe[9],  p3y = pe[10], p3z = pe[11];

    float cdx = p1x - p0x, cdy = p1y - p0y, cdz = p1z - p0z;
    float ax = cdx + 1e-6f, ay = cdy + 1e-6f, az = cdz + 1e-6f;
    float clen = sqrtf(ax * ax + ay * ay + az * az);

    int numh = (int)floorf(clen / 0.05f);
    numh = numh < 2 ? 2 : (numh > 1000 ? 1000 : numh);

    float dx = cdx / clen, dy = cdy / clen, dz = cdz / clen;
    float nxd = p3x - p1x, nyd = p3y - p1y, nzd = p3z - p1z;

    float cnx = dy * nzd - dz * nyd;
    float cny = dz * nxd - dx * nzd;
    float cnz = dx * nyd - dy * nxd;
    float nn = sqrtf(cnx * cnx + cny * cny + cnz * cnz) + 1e-6f;
    cnx /= nn; cny /= nn; cnz /= nn;
    if (cnz > 0.0f) { cnx = -cnx; cny = -cny; cnz = -cnz; }

    float ux = cny * dz - cnz * dy;
    float uy = cnz * dx - cnx * dz;
    float uz = cnx * dy - cny * dx;
    float un = sqrtf(ux * ux + uy * uy + uz * uz) + 1e-6f;
    ux /= un; uy /= un; uz /= un;

    if (threadIdx.x == 0) {
        float pxd = p0x - p2x, pyd = p0y - p2y, pzd = p0z - p2z;
        float pnx = pyd * dz - pzd * dy;
        float pny = pzd * dx - pxd * dz;
        float pnz = pxd * dy - pyd * dx;
        float pn = sqrtf(pnx * pnx + pny * pny + pnz * pnz) + 1e-6f;
        float nterm = 1.0f - (cnx * pnx + cny * pny + cnz * pnz) / pn;

        float ox = p0y * p1z - p0z * p1y;
        float oy = p0z * p1x - p0x * p1z;
        float oz = p0x * p1y - p0y * p1x;
        float on = sqrtf(ox * ox + oy * oy + oz * oz) + 1e-6f;
        float snp = fminf(fabsf((ux * ox + uy * oy + uz * oz) / on), 0.5f);
        float zterm = 1.0f - snp * 2.0f;

        int slot = e & (NSLOT - 1);
        atomicAdd(&g_nrm[slot], (double)nterm);
        atomicAdd(&g_nz[slot], (double)zterm);
        atomicAdd(&g_cnt[slot], (unsigned long long)numh);
    }

    // ---- per-warp hoisted projection constants ----
    // uv = M*(p0 + up*cy + dir*cx) = h + a*cx,  h = M*(p0+up*cy), a = M*dir
    float cy = (float)wid * ((1.0f / 9.0f) * 0.5f);
    float qx = fmaf(ux, cy, p0x);
    float qy = fmaf(uy, cy, p0y);
    float qz = fmaf(uz, cy, p0z);

    float K0 = __ldg(K1g + 0), K1 = __ldg(K1g + 1), K2 = __ldg(K1g + 2);
    float K3 = __ldg(K1g + 3), K4 = __ldg(K1g + 4), K5 = __ldg(K1g + 5);
    float K6 = __ldg(K1g + 6), K7 = __ldg(K1g + 7), K8 = __ldg(K1g + 8);
    float T[12];
#pragma unroll
    for (int j = 0; j < 12; j++) T[j] = g_T[j];

    // view 1: a1 = K*dir, h1 = K*q
    float a1u = K0 * dx + K1 * dy + K2 * dz;
    float a1v = K3 * dx + K4 * dy + K5 * dz;
    float a1w = K6 * dx + K7 * dy + K8 * dz;
    float h1u = K0 * qx + K1 * qy + K2 * qz;
    float h1v = K3 * qx + K4 * qy + K5 * qz;
    float h1w = K6 * qx + K7 * qy + K8 * qz;
    // view 2: a2 = T[:, :3]*dir, h2 = T*[q,1]
    float a2u = T[0] * dx + T[1] * dy + T[2] * dz;
    float a2v = T[4] * dx + T[5] * dy + T[6] * dz;
    float a2w = T[8] * dx + T[9] * dy + T[10] * dz;
    float h2u = fmaf(T[0], qx, fmaf(T[1], qy, fmaf(T[2], qz, T[3])));
    float h2v = fmaf(T[4], qx, fmaf(T[5], qy, fmaf(T[6], qz, T[7])));
    float h2w = fmaf(T[8], qx, fmaf(T[9], qy, fmaf(T[10], qz, T[11])));

    float stepx = clen / (float)(numh - 1);
    float lsum = 0.0f;

    float fix = (float)lane;
    for (int ix = lane; ix < numh; ix += 32, fix += 32.0f) {
        float cx = fix * stepx;

        float u1 = fmaf(a1u, cx, h1u);
        float v1 = fmaf(a1v, cx, h1v);
        float w1 = fmaf(a1w, cx, h1w);
        float iw1 = 1.0f / w1;
        float uu1 = fminf(fmaxf(u1 * iw1, 0.0f), 0.999999f);
        float vv1 = fminf(fmaxf(v1 * iw1, 0.0f), 0.999999f);

        float u2 = fmaf(a2u, cx, h2u);
        float v2 = fmaf(a2v, cx, h2v);
        float w2 = fmaf(a2w, cx, h2w);
        float iw2 = 1.0f / w2;
        float uu2 = fminf(fmaxf(u2 * iw2, 0.0f), 0.999999f);
        float vv2 = fminf(fmaxf(v2 * iw2, 0.0f), 0.999999f);

        float3 s1 = bilerp(g_img1, uu1, vv1);
        float3 s2 = bilerp(g_img2, uu2, vv2);
        float d0 = s1.x - s2.x, d1 = s1.y - s2.y, d2 = s1.z - s2.z;
        lsum = fmaf(d0, d0, fmaf(d1, d1, fmaf(d2, d2, lsum)));
    }

    // reduction: warp shuffle -> shared(10) -> thread 0 -> one double atomic
#pragma unroll
    for (int o = 16; o > 0; o >>= 1) lsum += __shfl_down_sync(0xffffffffu, lsum, o);
    __shared__ float ws[10];
    if (lane == 0) ws[wid] = lsum;
    __syncthreads();
    if (threadIdx.x == 0) {
        float s = 0.0f;
#pragma unroll
        for (int j = 0; j < 10; j++) s += ws[j];
        atomicAdd(&g_sim[e & (NSLOT - 1)], (double)s);
    }
}

// ---------------- finalize (parallel: 32 threads, shuffle reduce) ----------------
__global__ void k_final(float* __restrict__ out, int N) {
    int t = threadIdx.x;
    double sim = g_sim[t], nrm = g_nrm[t], nz = g_nz[t];
    unsigned long long cnt = g_cnt[t];
#pragma unroll
    for (int o = 16; o > 0; o >>= 1) {
        sim += __shfl_down_sync(0xffffffffu, sim, o);
        nrm += __shfl_down_sync(0xffffffffu, nrm, o);
        nz  += __shfl_down_sync(0xffffffffu, nz,  o);
        cnt += __shfl_down_sync(0xffffffffu, cnt, o);
    }
    if (t == 0) {
        double npts = (double)cnt * (double)NUM_V;
        out[0] = (float)(sim / (npts * 3.0));
        out[1] = (float)(nrm / (2.0 * (double)N));
        out[2] = (float)(nz / (double)N);
    }
}

// ---------------- launch ----------------
extern "C" void kernel_launch(void* const* d_in, const int* in_sizes, int n_in,
                              void* d_out, int out_size) {
    const float* ep   = (const float*)d_in[0];
    const float* K1   = (const float*)d_in[1];
    const float* K2   = (const float*)d_in[2];
    const float* E1   = (const float*)d_in[3];
    const float* E2   = (const float*)d_in[4];
    const float* rgb1 = (const float*)d_in[5];
    const float* rgb2 = (const float*)d_in[6];

    int N = in_sizes[0] / 12;

    k_init<<<1, 32>>>(K2, E1, E2);
    k_pack<<<(2 * HW + 255) / 256, 256>>>(rgb1, rgb2);
    k_sample<<<N, 320>>>(ep, K1);
    k_final<<<1, 32>>>((float*)d_out, N);
}

// round 15
// speedup vs baseline: 1.2763x; 1.2763x over previous
#include <cuda_runtime.h>
#include <math.h>

#define IMG_H 1500
#define IMG_W 2000
#define HW    (IMG_H * IMG_W)
#define NUM_V 10
#define NSLOT 32

// ---------------- device scratch (static; no runtime allocation) ----------------
// Quad layout: entry (x,y) = uint4 with the full 2x2 bilinear footprint.
//   .x = pixel(x,y)  .y = pixel(x+1,y)  .z = pixel(x,y+1)  .w = pixel(x+1,y+1)
// Each pixel packs r/g/b as 10-bit fixed point: (r<<20)|(g<<10)|b.
__device__ uint4 g_img1[HW];   // 48 MB
__device__ uint4 g_img2[HW];   // 48 MB
__device__ double g_sim[NSLOT];
__device__ double g_nrm[NSLOT];
__device__ double g_nz[NSLOT];
__device__ unsigned long long g_cnt[NSLOT];
__device__ float  g_T[12];     // rows 0..2 of K2h @ E2 @ inv(E1)

// ---------------- init: fp32, parallel prefetch, fast -----------------------
__global__ void k_init(const float* __restrict__ K2,
                       const float* __restrict__ E1,
                       const float* __restrict__ E2) {
    __shared__ float sE1[16], sE2[16], sK2[9];
    int t = threadIdx.x;
    if (t < 16) sE1[t] = E1[t];
    if (t < 16) sE2[t] = E2[t];
    if (t < 9)  sK2[t] = K2[t];
    if (t < NSLOT) { g_sim[t] = 0.0; g_nrm[t] = 0.0; g_nz[t] = 0.0; g_cnt[t] = 0ull; }
    __syncthreads();

    if (t == 0) {
        float a[4][8];
        for (int i = 0; i < 4; i++)
            for (int j = 0; j < 4; j++) {
                a[i][j] = sE1[i * 4 + j];
                a[i][4 + j] = (i == j) ? 1.0f : 0.0f;
            }
        for (int c = 0; c < 4; c++) {
            int p = c; float mx = fabsf(a[c][c]);
            for (int r = c + 1; r < 4; r++) {
                float v = fabsf(a[r][c]);
                if (v > mx) { mx = v; p = r; }
            }
            if (p != c)
                for (int j = 0; j < 8; j++) { float tmp = a[c][j]; a[c][j] = a[p][j]; a[p][j] = tmp; }
            float ipv = 1.0f / a[c][c];
            for (int j = 0; j < 8; j++) a[c][j] *= ipv;
            for (int r = 0; r < 4; r++)
                if (r != c) {
                    float f = a[r][c];
                    for (int j = 0; j < 8; j++) a[r][j] = fmaf(-f, a[c][j], a[r][j]);
                }
        }
        float M[4][4];
        for (int i = 0; i < 4; i++)
            for (int j = 0; j < 4; j++) {
                float s = 0.0f;
                for (int k = 0; k < 4; k++) s = fmaf(sE2[i * 4 + k], a[k][4 + j], s);
                M[i][j] = s;
            }
        for (int r = 0; r < 3; r++)
            for (int j = 0; j < 4; j++) {
                float s = 0.0f;
                for (int k = 0; k < 3; k++) s = fmaf(sK2[r * 3 + k], M[k][j], s);
                g_T[r * 4 + j] = s;
            }
    }
}

__device__ __forceinline__ unsigned int pack10(float r, float g, float b) {
    unsigned int qr = min(1023u, __float2uint_rn(r * 1023.0f));
    unsigned int qg = min(1023u, __float2uint_rn(g * 1023.0f));
    unsigned int qb = min(1023u, __float2uint_rn(b * 1023.0f));
    return (qr << 20) | (qg << 10) | qb;
}

// ---------------- pack both planar images -> 2x2 quad entries -------------------
__global__ void __launch_bounds__(256) k_pack(const float* __restrict__ r1,
                                              const float* __restrict__ r2) {
    int i = blockIdx.x * blockDim.x + threadIdx.x;
    if (i >= 2 * HW) return;
    const float* src = (i < HW) ? r1 : r2;
    uint4* dst       = (i < HW) ? g_img1 : g_img2;
    int j = (i < HW) ? i : i - HW;
    int x = j % IMG_W, y = j / IMG_W;
    int x1 = x + 1 < IMG_W ? x + 1 : IMG_W - 1;
    int y1 = y + 1 < IMG_H ? y + 1 : IMG_H - 1;

    int i00 = y * IMG_W + x,   i01 = y * IMG_W + x1;
    int i10 = y1 * IMG_W + x,  i11 = y1 * IMG_W + x1;

    uint4 v;
    v.x = pack10(src[i00], src[i00 + HW], src[i00 + 2 * HW]);
    v.y = pack10(src[i01], src[i01 + HW], src[i01 + 2 * HW]);
    v.z = pack10(src[i10], src[i10 + HW], src[i10 + 2 * HW]);
    v.w = pack10(src[i11], src[i11 + HW], src[i11 + 2 * HW]);
    dst[j] = v;
}

// ---------------- bilinear sample: ONE LDG.128 per sample ----------------
__device__ __forceinline__ float3 bilerp(const uint4* __restrict__ im, float uu, float vv) {
    float x = uu * (float)(IMG_W - 1);
    float y = vv * (float)(IMG_H - 1);
    float fx = floorf(x), fy = floorf(y);
    float wx = x - fx, wy = y - fy;
    int b = (int)fy * IMG_W + (int)fx;        // fx<=W-2, fy<=H-2 guaranteed by clip

    uint4 q = __ldg(im + b);

    const float s = 1.0f / 1023.0f;
    float w00 = (1.0f - wx) * (1.0f - wy) * s;
    float w01 = wx * (1.0f - wy) * s;
    float w10 = (1.0f - wx) * wy * s;
    float w11 = wx * wy * s;

    float3 r;
    r.x = w00 * (float)(q.x >> 20)
        + w01 * (float)(q.y >> 20)
        + w10 * (float)(q.z >> 20)
        + w11 * (float)(q.w >> 20);
    r.y = w00 * (float)((q.x >> 10) & 1023u)
        + w01 * (float)((q.y >> 10) & 1023u)
        + w10 * (float)((q.z >> 10) & 1023u)
        + w11 * (float)((q.w >> 10) & 1023u);
    r.z = w00 * (float)(q.x & 1023u)
        + w01 * (float)(q.y & 1023u)
        + w10 * (float)(q.z & 1023u)
        + w11 * (float)(q.w & 1023u);
    return r;
}

// ---------------- per-edge prep + sampling + all losses (1 block per edge) -------
__global__ void __launch_bounds__(128) k_sample(const float* __restrict__ ep,
                                                const float* __restrict__ K1g) {
    int e = blockIdx.x;
    const float* pe = ep + (size_t)e * 12;
    float p0x = pe[0],  p0y = pe[1],  p0z = pe[2];
    float p1x = pe[3],  p1y = pe[4],  p1z = pe[5];
    float p2x = pe[6],  p2y = pe[7],  p2z = pe[8];
    float p3x = pe[9],  p3y = pe[10], p3z = pe[11];

    float cdx = p1x - p0x, cdy = p1y - p0y, cdz = p1z - p0z;
    float ax = cdx + 1e-6f, ay = cdy + 1e-6f, az = cdz + 1e-6f;
    float clen = sqrtf(ax * ax + ay * ay + az * az);

    int numh = (int)floorf(clen / 0.05f);
    numh = numh < 2 ? 2 : (numh > 1000 ? 1000 : numh);

    float dx = cdx / clen, dy = cdy / clen, dz = cdz / clen;
    float nxd = p3x - p1x, nyd = p3y - p1y, nzd = p3z - p1z;

    float cnx = dy * nzd - dz * nyd;
    float cny = dz * nxd - dx * nzd;
    float cnz = dx * nyd - dy * nxd;
    float nn = sqrtf(cnx * cnx + cny * cny + cnz * cnz) + 1e-6f;
    cnx /= nn; cny /= nn; cnz /= nn;
    if (cnz > 0.0f) { cnx = -cnx; cny = -cny; cnz = -cnz; }

    float ux = cny * dz - cnz * dy;
    float uy = cnz * dx - cnx * dz;
    float uz = cnx * dy - cny * dx;
    float un = sqrtf(ux * ux + uy * uy + uz * uz) + 1e-6f;
    ux /= un; uy /= un; uz /= un;

    if (threadIdx.x == 0) {
        float pxd = p0x - p2x, pyd = p0y - p2y, pzd = p0z - p2z;
        float pnx = pyd * dz - pzd * dy;
        float pny = pzd * dx - pxd * dz;
        float pnz = pxd * dy - pyd * dx;
        float pn = sqrtf(pnx * pnx + pny * pny + pnz * pnz) + 1e-6f;
        float nterm = 1.0f - (cnx * pnx + cny * pny + cnz * pnz) / pn;

        float ox = p0y * p1z - p0z * p1y;
        float oy = p0z * p1x - p0x * p1z;
        float oz = p0x * p1y - p0y * p1x;
        float on = sqrtf(ox * ox + oy * oy + oz * oz) + 1e-6f;
        float snp = fminf(fabsf((ux * ox + uy * oy + uz * oz) / on), 0.5f);
        float zterm = 1.0f - snp * 2.0f;

        int slot = e & (NSLOT - 1);
        atomicAdd(&g_nrm[slot], (double)nterm);
        atomicAdd(&g_nz[slot], (double)zterm);
        atomicAdd(&g_cnt[slot], (unsigned long long)numh);
    }

    float K0 = __ldg(K1g + 0), K1 = __ldg(K1g + 1), K2 = __ldg(K1g + 2);
    float K3 = __ldg(K1g + 3), K4 = __ldg(K1g + 4), K5 = __ldg(K1g + 5);
    float K6 = __ldg(K1g + 6), K7 = __ldg(K1g + 7), K8 = __ldg(K1g + 8);
    float T[12];
#pragma unroll
    for (int j = 0; j < 12; j++) T[j] = g_T[j];

    // ---- per-edge projection constants: uv = h + a*cx + b*cy ----
    // view 1 (K1):  a1 = K*dir, b1 = K*up, h1 = K*p0
    float a1u = K0 * dx + K1 * dy + K2 * dz;
    float a1v = K3 * dx + K4 * dy + K5 * dz;
    float a1w = K6 * dx + K7 * dy + K8 * dz;
    float b1u = K0 * ux + K1 * uy + K2 * uz;
    float b1v = K3 * ux + K4 * uy + K5 * uz;
    float b1w = K6 * ux + K7 * uy + K8 * uz;
    float h1u = K0 * p0x + K1 * p0y + K2 * p0z;
    float h1v = K3 * p0x + K4 * p0y + K5 * p0z;
    float h1w = K6 * p0x + K7 * p0y + K8 * p0z;
    // view 2 (T):   a2 = T3x3*dir, b2 = T3x3*up, h2 = T3x3*p0 + T[:,3]
    float a2u = T[0] * dx + T[1] * dy + T[2] * dz;
    float a2v = T[4] * dx + T[5] * dy + T[6] * dz;
    float a2w = T[8] * dx + T[9] * dy + T[10] * dz;
    float b2u = T[0] * ux + T[1] * uy + T[2] * uz;
    float b2v = T[4] * ux + T[5] * uy + T[6] * uz;
    float b2w = T[8] * ux + T[9] * uy + T[10] * uz;
    float h2u = fmaf(T[0], p0x, fmaf(T[1], p0y, fmaf(T[2], p0z, T[3])));
    float h2v = fmaf(T[4], p0x, fmaf(T[5], p0y, fmaf(T[6], p0z, T[7])));
    float h2w = fmaf(T[8], p0x, fmaf(T[9], p0y, fmaf(T[10], p0z, T[11])));

    int total = numh * NUM_V;
    float inv_denom = 1.0f / (float)(numh - 1);
    const float inv9h = (1.0f / 9.0f) * 0.5f;
    float lsum = 0.0f;

    for (int t = threadIdx.x; t < total; t += 128) {
        int ix = t / NUM_V;
        int dv = t - ix * NUM_V;
        float cx = ((float)ix * inv_denom) * clen;
        float cy = (float)dv * inv9h;

        float u1 = fmaf(a1u, cx, fmaf(b1u, cy, h1u));
        float v1 = fmaf(a1v, cx, fmaf(b1v, cy, h1v));
        float w1 = fmaf(a1w, cx, fmaf(b1w, cy, h1w));
        float iw1 = 1.0f / w1;
        float uu1 = fminf(fmaxf(u1 * iw1, 0.0f), 0.999999f);
        float vv1 = fminf(fmaxf(v1 * iw1, 0.0f), 0.999999f);

        float u2 = fmaf(a2u, cx, fmaf(b2u, cy, h2u));
        float v2 = fmaf(a2v, cx, fmaf(b2v, cy, h2v));
        float w2 = fmaf(a2w, cx, fmaf(b2w, cy, h2w));
        float iw2 = 1.0f / w2;
        float uu2 = fminf(fmaxf(u2 * iw2, 0.0f), 0.999999f);
        float vv2 = fminf(fmaxf(v2 * iw2, 0.0f), 0.999999f);

        float3 s1 = bilerp(g_img1, uu1, vv1);
        float3 s2 = bilerp(g_img2, uu2, vv2);
        float d0 = s1.x - s2.x, d1 = s1.y - s2.y, d2 = s1.z - s2.z;
        lsum = fmaf(d0, d0, fmaf(d1, d1, fmaf(d2, d2, lsum)));
    }

#pragma unroll
    for (int o = 16; o > 0; o >>= 1) lsum += __shfl_down_sync(0xffffffffu, lsum, o);
    __shared__ float ws[4];
    int lane = threadIdx.x & 31, w = threadIdx.x >> 5;
    if (lane == 0) ws[w] = lsum;
    __syncthreads();
    if (threadIdx.x == 0) {
        float s = ws[0] + ws[1] + ws[2] + ws[3];
        atomicAdd(&g_sim[e & (NSLOT - 1)], (double)s);
    }
}

// ---------------- finalize (parallel: 32 threads, shuffle reduce) ----------------
__global__ void k_final(float* __restrict__ out, int N) {
    int t = threadIdx.x;
    double sim = g_sim[t], nrm = g_nrm[t], nz = g_nz[t];
    unsigned long long cnt = g_cnt[t];
#pragma unroll
    for (int o = 16; o > 0; o >>= 1) {
        sim += __shfl_down_sync(0xffffffffu, sim, o);
        nrm += __shfl_down_sync(0xffffffffu, nrm, o);
        nz  += __shfl_down_sync(0xffffffffu, nz,  o);
        cnt += __shfl_down_sync(0xffffffffu, cnt, o);
    }
    if (t == 0) {
        double npts = (double)cnt * (double)NUM_V;
        out[0] = (float)(sim / (npts * 3.0));
        out[1] = (float)(nrm / (2.0 * (double)N));
        out[2] = (float)(nz / (double)N);
    }
}

// ---------------- launch ----------------
extern "C" void kernel_launch(void* const* d_in, const int* in_sizes, int n_in,
                              void* d_out, int out_size) {
    const float* ep   = (const float*)d_in[0];
    const float* K1   = (const float*)d_in[1];
    const float* K2   = (const float*)d_in[2];
    const float* E1   = (const float*)d_in[3];
    const float* E2   = (const float*)d_in[4];
    const float* rgb1 = (const float*)d_in[5];
    const float* rgb2 = (const float*)d_in[6];

    int N = in_sizes[0] / 12;

    k_init<<<1, 32>>>(K2, E1, E2);
    k_pack<<<(2 * HW + 255) / 256, 256>>>(rgb1, rgb2);
    k_sample<<<N, 128>>>(ep, K1);
    k_final<<<1, 32>>>((float*)d_out, N);
}